// round 4
// baseline (speedup 1.0000x reference)
#include <cuda_runtime.h>

#define N_NODES 50000
#define N_EDGES 800000
#define HID     128
#define NH      8
#define HD      16

// ---------------- scratch (device globals; no allocation allowed) ----------------
__device__ float g_wfold[HID * 16];     // [k][c]: c<8 -> src head c, c>=8 -> dst head c-8
__device__ float g_bfold[16];
__device__ float g_alpha[N_NODES * 16]; // [n][c]: 0..7 alpha_src, 8..15 alpha_dst
__device__ int   g_segmax_i[N_NODES * NH]; // float-bits as int; init 0 == 0.0f floor
__device__ float g_segsum[N_NODES * NH];
__device__ int   g_is64;                // edge_index dtype flag
__device__ int   g_row[N_EDGES];
__device__ int   g_col[N_EDGES];

// ---------------- K-2: detect edge_index dtype ----------------
// If the buffer is really int64, every 8-byte word is a node id in [0, N).
// If it is int32, an 8-byte word is lo + hi*2^32 with hi ~uniform[0,N): the
// probability that 64 consecutive words all have hi==0 is ~(2e-5)^64 ~ 0.
__global__ void detect_kernel(const void* __restrict__ ei) {
    if (threadIdx.x != 0 || blockIdx.x != 0) return;
    const long long* p = (const long long*)ei;
    int ok = 1;
    for (int i = 0; i < 64; i++) {
        long long v = p[i];
        if (v < 0 || v >= N_NODES) { ok = 0; break; }
    }
    g_is64 = ok;
}

// ---------------- K-1: unpack edge_index to flat int32 row/col ----------------
__global__ void convert_kernel(const void* __restrict__ ei) {
    int e = blockIdx.x * blockDim.x + threadIdx.x;
    if (e >= N_EDGES) return;
    if (g_is64) {
        const long long* p = (const long long*)ei;
        g_row[e] = (int)__ldg(p + e);
        g_col[e] = (int)__ldg(p + N_EDGES + e);
    } else {
        const int* p = (const int*)ei;
        g_row[e] = __ldg(p + e);
        g_col[e] = __ldg(p + N_EDGES + e);
    }
}

// ---------------- K0: fold node_w/node_b with att_w ----------------
// alpha_src[n,h] = (x @ node_w[:, h*32 : h*32+16]) . att_w[h, 0:16]
//               = x . (node_w-slice @ att_w-slice)  -> fold into 128x16 matrix.
__global__ void fold_kernel(const float* __restrict__ node_w,
                            const float* __restrict__ node_b,
                            const float* __restrict__ att_w) {
    int tid = threadIdx.x;
    for (int i = tid; i < HID * 16; i += blockDim.x) {
        int k = i >> 4;
        int c = i & 15;
        int h = c & 7;
        int off = (c < 8) ? 0 : HD;
        float s = 0.f;
#pragma unroll
        for (int d = 0; d < HD; d++)
            s += node_w[k * (2 * HID) + h * (2 * HD) + off + d] *
                 att_w[h * (2 * HD) + off + d];
        g_wfold[i] = s;
    }
    if (tid < 16) {
        int c = tid;
        int h = c & 7;
        int off = (c < 8) ? 0 : HD;
        float s = 0.f;
#pragma unroll
        for (int d = 0; d < HD; d++)
            s += node_b[h * (2 * HD) + off + d] * att_w[h * (2 * HD) + off + d];
        g_bfold[c] = s;
    }
}

// ---------------- K1: alpha[n][c] = x[n,:] @ wfold[:,c] + bfold[c] ----------------
__global__ void alpha_kernel(const float* __restrict__ x) {
    int g = blockIdx.x * blockDim.x + threadIdx.x;   // N_NODES*16 threads
    int n = g >> 4;
    int c = g & 15;
    if (n >= N_NODES) return;
    const float* xr = x + (size_t)n * HID;
    float acc = g_bfold[c];
#pragma unroll 16
    for (int k = 0; k < HID; k++)
        acc += __ldg(xr + k) * g_wfold[k * 16 + c];
    g_alpha[g] = acc;
}

// ---------------- K2: zero segmax/segsum and d_out ----------------
__global__ void zero_kernel(float* __restrict__ out) {
    int g = blockIdx.x * blockDim.x + threadIdx.x;
    const int OUT4 = N_NODES * HID / 4;   // 1.6M
    if (g < OUT4) ((float4*)out)[g] = make_float4(0.f, 0.f, 0.f, 0.f);
    const int SEG4 = N_NODES * NH / 4;    // 100k
    if (g < SEG4) {
        ((int4*)g_segmax_i)[g] = make_int4(0, 0, 0, 0);
        ((float4*)g_segsum)[g] = make_float4(0.f, 0.f, 0.f, 0.f);
    }
}

// ---------------- K3: one thread per edge -> leaky score + atomicMax ----------------
// seg_max is floored at 0 (init 0). Stored value always >= 0, so signed-int
// compare of float bits is order-correct; negative candidates never win.
__global__ void scoremax_kernel() {
    int e = blockIdx.x * blockDim.x + threadIdx.x;
    if (e >= N_EDGES) return;
    int row = g_row[e];
    int col = g_col[e];
    float4 as0 = *(const float4*)(g_alpha + row * 16);
    float4 as1 = *(const float4*)(g_alpha + row * 16 + 4);
    float4 ad0 = *(const float4*)(g_alpha + col * 16 + 8);
    float4 ad1 = *(const float4*)(g_alpha + col * 16 + 12);
    float sa[8] = {as0.x, as0.y, as0.z, as0.w, as1.x, as1.y, as1.z, as1.w};
    float da[8] = {ad0.x, ad0.y, ad0.z, ad0.w, ad1.x, ad1.y, ad1.z, ad1.w};
    int* mrow = g_segmax_i + col * NH;
#pragma unroll
    for (int h = 0; h < NH; h++) {
        float s = sa[h] + da[h];
        s = (s >= 0.f) ? s : 0.2f * s;
        atomicMax(mrow + h, __float_as_int(s));
    }
}

// ---------------- K4: one thread per edge -> exp(s - max) + atomicAdd seg-sum ----------------
__global__ void expsum_kernel() {
    int e = blockIdx.x * blockDim.x + threadIdx.x;
    if (e >= N_EDGES) return;
    int row = g_row[e];
    int col = g_col[e];
    float4 as0 = *(const float4*)(g_alpha + row * 16);
    float4 as1 = *(const float4*)(g_alpha + row * 16 + 4);
    float4 ad0 = *(const float4*)(g_alpha + col * 16 + 8);
    float4 ad1 = *(const float4*)(g_alpha + col * 16 + 12);
    int4 m0 = *(const int4*)(g_segmax_i + col * NH);
    int4 m1 = *(const int4*)(g_segmax_i + col * NH + 4);
    float sa[8] = {as0.x, as0.y, as0.z, as0.w, as1.x, as1.y, as1.z, as1.w};
    float da[8] = {ad0.x, ad0.y, ad0.z, ad0.w, ad1.x, ad1.y, ad1.z, ad1.w};
    int   mi[8] = {m0.x, m0.y, m0.z, m0.w, m1.x, m1.y, m1.z, m1.w};
    float* srow = g_segsum + col * NH;
#pragma unroll
    for (int h = 0; h < NH; h++) {
        float s = sa[h] + da[h];
        s = (s >= 0.f) ? s : 0.2f * s;
        atomicAdd(srow + h, __expf(s - __int_as_float(mi[h])));
    }
}

// ---------------- K5: aggregation directly into d_out. One warp per edge. ----------------
// Lanes 0..7 recompute attn per head (all loads lane-coalesced); lane l handles
// dims {l,32+l,64+l,96+l} so gathers and REDs are full 128B warp transactions.
__global__ void agg_kernel(const float* __restrict__ x,
                           float* __restrict__ out) {
    int w = (blockIdx.x * blockDim.x + threadIdx.x) >> 5;
    int lane = threadIdx.x & 31;
    if (w >= N_EDGES) return;
    int row = g_row[w];
    int col = g_col[w];
    float attn = 0.f;
    if (lane < NH) {
        float s = g_alpha[row * 16 + lane] + g_alpha[col * 16 + 8 + lane];
        s = (s >= 0.f) ? s : 0.2f * s;
        float es = __expf(s - __int_as_float(g_segmax_i[col * NH + lane]));
        attn = __fdividef(es, g_segsum[col * NH + lane] + 1e-10f);
    }
    const float* xr = x + (size_t)row * HID;
    float* og = out + (size_t)col * HID;
#pragma unroll
    for (int i = 0; i < 4; i++) {
        int d = i * 32 + lane;
        int h = d >> 4;
        float a = __shfl_sync(0xffffffffu, attn, h);
        atomicAdd(og + d, __ldg(xr + d) * a);   // RED, no return
    }
}

// ---------------- K6: in-place out = out @ out_w + out_b (50000x128x128) ----------------
// Each block handles rows m0..m0+127; outputs depend only on those same rows,
// and all tile reads finish before the epilogue writes -> in-place is safe.
#define BM 128
#define BN 128
#define BK 16
#define TM 8
#define TN 8

__global__ void __launch_bounds__(256, 2)
out_gemm_kernel(const float* __restrict__ Wm,
                const float* __restrict__ bias,
                float* __restrict__ out) {
    __shared__ float As[BK][BM + 4];
    __shared__ float Bs[BK][BN];

    int tid = threadIdx.x;
    int tx = tid & 15;
    int ty = tid >> 4;
    int m0 = blockIdx.x * BM;

    float acc[TM][TN];
#pragma unroll
    for (int i = 0; i < TM; i++)
#pragma unroll
        for (int j = 0; j < TN; j++) acc[i][j] = 0.f;

    for (int k0 = 0; k0 < HID; k0 += BK) {
#pragma unroll
        for (int p = 0; p < 2; p++) {
            int fid = p * 256 + tid;
            int m = fid >> 2;
            int kq = fid & 3;
            int mg = m0 + m;
            float4 v = make_float4(0.f, 0.f, 0.f, 0.f);
            if (mg < N_NODES)
                v = *(const float4*)(out + (size_t)mg * HID + k0 + kq * 4);
            As[kq * 4 + 0][m] = v.x;
            As[kq * 4 + 1][m] = v.y;
            As[kq * 4 + 2][m] = v.z;
            As[kq * 4 + 3][m] = v.w;
        }
#pragma unroll
        for (int p = 0; p < 2; p++) {
            int idx4 = p * 256 + tid;
            int k = idx4 >> 5;
            int nq = idx4 & 31;
            *(float4*)&Bs[k][nq * 4] =
                *(const float4*)(Wm + (size_t)(k0 + k) * HID + nq * 4);
        }
        __syncthreads();

#pragma unroll
        for (int kk = 0; kk < BK; kk++) {
            float4 a0 = *(const float4*)&As[kk][ty * TM];
            float4 a1 = *(const float4*)&As[kk][ty * TM + 4];
            float4 b0 = *(const float4*)&Bs[kk][tx * TN];
            float4 b1 = *(const float4*)&Bs[kk][tx * TN + 4];
            float a[TM] = {a0.x, a0.y, a0.z, a0.w, a1.x, a1.y, a1.z, a1.w};
            float b[TN] = {b0.x, b0.y, b0.z, b0.w, b1.x, b1.y, b1.z, b1.w};
#pragma unroll
            for (int i = 0; i < TM; i++)
#pragma unroll
                for (int j = 0; j < TN; j++)
                    acc[i][j] += a[i] * b[j];
        }
        __syncthreads();
    }

#pragma unroll
    for (int i = 0; i < TM; i++) {
        int mg = m0 + ty * TM + i;
        if (mg < N_NODES) {
#pragma unroll
            for (int j = 0; j < TN; j += 4) {
                int n = tx * TN + j;
                float4 o;
                o.x = acc[i][j + 0] + __ldg(bias + n + 0);
                o.y = acc[i][j + 1] + __ldg(bias + n + 1);
                o.z = acc[i][j + 2] + __ldg(bias + n + 2);
                o.w = acc[i][j + 3] + __ldg(bias + n + 3);
                *(float4*)(out + (size_t)mg * HID + n) = o;
            }
        }
    }
}

// ---------------- launch: kernel launches ONLY ----------------
extern "C" void kernel_launch(void* const* d_in, const int* in_sizes, int n_in,
                              void* d_out, int out_size) {
    const float* x      = (const float*)d_in[0];
    const void*  ei     = d_in[1];
    const float* node_w = (const float*)d_in[2];
    const float* node_b = (const float*)d_in[3];
    const float* att_w  = (const float*)d_in[4];
    const float* out_w  = (const float*)d_in[5];
    const float* out_b  = (const float*)d_in[6];
    float*       out    = (float*)d_out;

    detect_kernel<<<1, 32>>>(ei);
    convert_kernel<<<(N_EDGES + 255) / 256, 256>>>(ei);

    fold_kernel<<<1, 256>>>(node_w, node_b, att_w);
    alpha_kernel<<<(N_NODES * 16 + 255) / 256, 256>>>(x);
    zero_kernel<<<(N_NODES * HID / 4 + 255) / 256, 256>>>(out);

    scoremax_kernel<<<(N_EDGES + 255) / 256, 256>>>();
    expsum_kernel<<<(N_EDGES + 255) / 256, 256>>>();

    agg_kernel<<<(N_EDGES * 32 + 255) / 256, 256>>>(x, out);

    out_gemm_kernel<<<(N_NODES + BM - 1) / BM, 256>>>(out_w, out_b, out);
}

// round 5
// speedup vs baseline: 1.1221x; 1.1221x over previous
#include <cuda_runtime.h>

#define N_NODES 50000
#define N_EDGES 800000
#define HID     128
#define NH      8
#define HD      16
#define NB_SCAN 196   // ceil(N_NODES/256)

// ---------------- scratch (device globals; no allocation allowed) ----------------
__device__ float g_wfoldT[16 * HID];    // [c][k] transposed folded weights
__device__ float g_bfold[16];
__device__ float g_alpha[N_NODES * 16]; // [n][c]: 0..7 alpha_src, 8..15 alpha_dst
__device__ int   g_is64;
__device__ int   g_row[N_EDGES];
__device__ int   g_col[N_EDGES];
__device__ int   g_deg[N_NODES];
__device__ int   g_ptr[N_NODES];        // CSR start per destination node
__device__ int   g_cursor[N_NODES];
__device__ int   g_bsum[NB_SCAN];
__device__ int   g_boff[NB_SCAN];
__device__ int   g_csrc[N_EDGES];       // CSR: source node of each incoming edge

// ---------------- K0: detect edge_index dtype ----------------
// int64 data: every 8-byte word is a node id in [0,N). int32 data: hi word of an
// 8-byte read is ~uniform[0,N); 64 consecutive zero-hi words has prob ~0.
__global__ void detect_kernel(const void* __restrict__ ei) {
    if (threadIdx.x != 0) return;
    const long long* p = (const long long*)ei;
    int ok = 1;
    for (int i = 0; i < 64; i++) {
        long long v = p[i];
        if (v < 0 || v >= N_NODES) { ok = 0; break; }
    }
    g_is64 = ok;
}

// ---------------- K1: zero degree histogram ----------------
__global__ void zdeg_kernel() {
    int i = blockIdx.x * blockDim.x + threadIdx.x;
    if (i < N_NODES) g_deg[i] = 0;
}

// ---------------- K2: unpack edge_index + degree histogram ----------------
__global__ void convert_kernel(const void* __restrict__ ei) {
    int e = blockIdx.x * blockDim.x + threadIdx.x;
    if (e >= N_EDGES) return;
    int r, c;
    if (g_is64) {
        const long long* p = (const long long*)ei;
        r = (int)__ldg(p + e);
        c = (int)__ldg(p + N_EDGES + e);
    } else {
        const int* p = (const int*)ei;
        r = __ldg(p + e);
        c = __ldg(p + N_EDGES + e);
    }
    g_row[e] = r;
    g_col[e] = c;
    atomicAdd(g_deg + c, 1);
}

// ---------------- K3..K5: exclusive scan of deg -> ptr ----------------
__global__ void scan1_kernel() {
    __shared__ int s[256];
    int i = blockIdx.x * 256 + threadIdx.x;
    int v = (i < N_NODES) ? g_deg[i] : 0;
    s[threadIdx.x] = v;
    __syncthreads();
#pragma unroll
    for (int off = 1; off < 256; off <<= 1) {
        int t = (threadIdx.x >= off) ? s[threadIdx.x - off] : 0;
        __syncthreads();
        s[threadIdx.x] += t;
        __syncthreads();
    }
    if (i < N_NODES) g_ptr[i] = s[threadIdx.x] - v;   // exclusive
    if (threadIdx.x == 255) g_bsum[blockIdx.x] = s[255];
}

__global__ void scan2_kernel() {
    __shared__ int s[256];
    int v = (threadIdx.x < NB_SCAN) ? g_bsum[threadIdx.x] : 0;
    s[threadIdx.x] = v;
    __syncthreads();
#pragma unroll
    for (int off = 1; off < 256; off <<= 1) {
        int t = (threadIdx.x >= off) ? s[threadIdx.x - off] : 0;
        __syncthreads();
        s[threadIdx.x] += t;
        __syncthreads();
    }
    if (threadIdx.x < NB_SCAN) g_boff[threadIdx.x] = s[threadIdx.x] - v;
}

__global__ void scan3_kernel() {
    int i = blockIdx.x * blockDim.x + threadIdx.x;
    if (i >= N_NODES) return;
    int p = g_ptr[i] + g_boff[i >> 8];
    g_ptr[i] = p;
    g_cursor[i] = p;
}

// ---------------- K6: scatter edges into CSR ----------------
__global__ void scatter_kernel() {
    int e = blockIdx.x * blockDim.x + threadIdx.x;
    if (e >= N_EDGES) return;
    int c = g_col[e];
    int pos = atomicAdd(g_cursor + c, 1);
    g_csrc[pos] = g_row[e];
}

// ---------------- K7: fold node_w/node_b with att_w (store transposed) ----------------
// alpha_src[n,h] = x[n,:] . (node_w[:, h*32:h*32+16] @ att_w[h,0:16]) -> 128x16 fold.
__global__ void fold_kernel(const float* __restrict__ node_w,
                            const float* __restrict__ node_b,
                            const float* __restrict__ att_w) {
    int tid = threadIdx.x;
    for (int i = tid; i < HID * 16; i += blockDim.x) {
        int k = i >> 4;
        int c = i & 15;
        int h = c & 7;
        int off = (c < 8) ? 0 : HD;
        float s = 0.f;
#pragma unroll
        for (int d = 0; d < HD; d++)
            s += node_w[k * (2 * HID) + h * (2 * HD) + off + d] *
                 att_w[h * (2 * HD) + off + d];
        g_wfoldT[c * HID + k] = s;
    }
    if (tid < 16) {
        int c = tid;
        int h = c & 7;
        int off = (c < 8) ? 0 : HD;
        float s = 0.f;
#pragma unroll
        for (int d = 0; d < HD; d++)
            s += node_b[h * (2 * HD) + off + d] * att_w[h * (2 * HD) + off + d];
        g_bfold[c] = s;
    }
}

// ---------------- K8: alpha[n][c] = x[n,:] . wfoldT[c,:] + bfold[c] ----------------
// 16 threads per node, float4-vectorized: x float4 broadcasts within the group.
__global__ void alpha_kernel(const float* __restrict__ x) {
    int g = blockIdx.x * blockDim.x + threadIdx.x;   // N_NODES*16 threads
    int n = g >> 4;
    int c = g & 15;
    if (n >= N_NODES) return;
    const float4* xr = (const float4*)(x + (size_t)n * HID);
    const float4* wr = (const float4*)(g_wfoldT + c * HID);
    float acc = g_bfold[c];
#pragma unroll 8
    for (int k = 0; k < HID / 4; k++) {
        float4 xv = __ldg(xr + k);
        float4 wv = wr[k];
        acc += xv.x * wv.x + xv.y * wv.y + xv.z * wv.z + xv.w * wv.w;
    }
    g_alpha[g] = acc;
}

// ---------------- K9: fused GAT — online softmax + aggregation, warp per node ----------------
// Lanes 0..7 hold per-head running max m (init 0 = reference's 0-floor) and sum.
// Lane l accumulates dims 4l..4l+3, all in head l>>2; factors shuffled from lane l>>2.
__global__ void gat_kernel(const float* __restrict__ x,
                           float* __restrict__ out) {
    int n = (blockIdx.x * blockDim.x + threadIdx.x) >> 5;
    int lane = threadIdx.x & 31;
    if (n >= N_NODES) return;

    int base = g_ptr[n];
    int deg  = g_deg[n];
    float ad = (lane < NH) ? g_alpha[n * 16 + 8 + lane] : 0.f;

    float m = 0.f, ssum = 0.f;                 // per-head on lanes 0..7
    float a0 = 0.f, a1 = 0.f, a2 = 0.f, a3 = 0.f;
    int hsrc = lane >> 2;                      // head owner lane for my 4 dims

    for (int j = 0; j < deg; j++) {
        int row = __ldg(g_csrc + base + j);    // broadcast across warp
        float sc = 0.f, mnew = 0.f;
        if (lane < NH) {
            sc = g_alpha[row * 16 + lane] + ad;
            sc = (sc >= 0.f) ? sc : 0.2f * sc;
            mnew = fmaxf(m, sc);
        }
        bool changed = __any_sync(0xffffffffu, (lane < NH) && (mnew > m));
        float p = (lane < NH) ? __expf(sc - mnew) : 0.f;
        float4 xv = *(const float4*)(x + (size_t)row * HID + 4 * lane);
        if (changed) {
            float f = (lane < NH) ? __expf(m - mnew) : 1.f;
            m = mnew;
            ssum = ssum * f + p;
            float f_h = __shfl_sync(0xffffffffu, f, hsrc);
            float p_h = __shfl_sync(0xffffffffu, p, hsrc);
            a0 = a0 * f_h + p_h * xv.x;
            a1 = a1 * f_h + p_h * xv.y;
            a2 = a2 * f_h + p_h * xv.z;
            a3 = a3 * f_h + p_h * xv.w;
        } else {
            ssum += p;
            float p_h = __shfl_sync(0xffffffffu, p, hsrc);
            a0 += p_h * xv.x;
            a1 += p_h * xv.y;
            a2 += p_h * xv.z;
            a3 += p_h * xv.w;
        }
    }

    float s_h = __shfl_sync(0xffffffffu, ssum, hsrc);
    float inv = __fdividef(1.f, s_h + 1e-10f);
    float4 o = make_float4(a0 * inv, a1 * inv, a2 * inv, a3 * inv);
    *(float4*)(out + (size_t)n * HID + 4 * lane) = o;
}

// ---------------- K10: in-place out = out @ out_w + out_b (50000x128x128) ----------------
#define BM 128
#define BN 128
#define BK 16
#define TM 8
#define TN 8

__global__ void __launch_bounds__(256, 2)
out_gemm_kernel(const float* __restrict__ Wm,
                const float* __restrict__ bias,
                float* __restrict__ out) {
    __shared__ float As[BK][BM + 4];
    __shared__ float Bs[BK][BN];

    int tid = threadIdx.x;
    int tx = tid & 15;
    int ty = tid >> 4;
    int m0 = blockIdx.x * BM;

    float acc[TM][TN];
#pragma unroll
    for (int i = 0; i < TM; i++)
#pragma unroll
        for (int j = 0; j < TN; j++) acc[i][j] = 0.f;

    for (int k0 = 0; k0 < HID; k0 += BK) {
#pragma unroll
        for (int p = 0; p < 2; p++) {
            int fid = p * 256 + tid;
            int m = fid >> 2;
            int kq = fid & 3;
            int mg = m0 + m;
            float4 v = make_float4(0.f, 0.f, 0.f, 0.f);
            if (mg < N_NODES)
                v = *(const float4*)(out + (size_t)mg * HID + k0 + kq * 4);
            As[kq * 4 + 0][m] = v.x;
            As[kq * 4 + 1][m] = v.y;
            As[kq * 4 + 2][m] = v.z;
            As[kq * 4 + 3][m] = v.w;
        }
#pragma unroll
        for (int p = 0; p < 2; p++) {
            int idx4 = p * 256 + tid;
            int k = idx4 >> 5;
            int nq = idx4 & 31;
            *(float4*)&Bs[k][nq * 4] =
                *(const float4*)(Wm + (size_t)(k0 + k) * HID + nq * 4);
        }
        __syncthreads();

#pragma unroll
        for (int kk = 0; kk < BK; kk++) {
            float4 a0 = *(const float4*)&As[kk][ty * TM];
            float4 a1 = *(const float4*)&As[kk][ty * TM + 4];
            float4 b0 = *(const float4*)&Bs[kk][tx * TN];
            float4 b1 = *(const float4*)&Bs[kk][tx * TN + 4];
            float a[TM] = {a0.x, a0.y, a0.z, a0.w, a1.x, a1.y, a1.z, a1.w};
            float b[TN] = {b0.x, b0.y, b0.z, b0.w, b1.x, b1.y, b1.z, b1.w};
#pragma unroll
            for (int i = 0; i < TM; i++)
#pragma unroll
                for (int j = 0; j < TN; j++)
                    acc[i][j] += a[i] * b[j];
        }
        __syncthreads();
    }

#pragma unroll
    for (int i = 0; i < TM; i++) {
        int mg = m0 + ty * TM + i;
        if (mg < N_NODES) {
#pragma unroll
            for (int j = 0; j < TN; j += 4) {
                int nn = tx * TN + j;
                float4 o;
                o.x = acc[i][j + 0] + __ldg(bias + nn + 0);
                o.y = acc[i][j + 1] + __ldg(bias + nn + 1);
                o.z = acc[i][j + 2] + __ldg(bias + nn + 2);
                o.w = acc[i][j + 3] + __ldg(bias + nn + 3);
                *(float4*)(out + (size_t)mg * HID + nn) = o;
            }
        }
    }
}

// ---------------- launch: kernel launches ONLY ----------------
extern "C" void kernel_launch(void* const* d_in, const int* in_sizes, int n_in,
                              void* d_out, int out_size) {
    const float* x      = (const float*)d_in[0];
    const void*  ei     = d_in[1];
    const float* node_w = (const float*)d_in[2];
    const float* node_b = (const float*)d_in[3];
    const float* att_w  = (const float*)d_in[4];
    const float* out_w  = (const float*)d_in[5];
    const float* out_b  = (const float*)d_in[6];
    float*       out    = (float*)d_out;

    detect_kernel<<<1, 32>>>(ei);
    zdeg_kernel<<<NB_SCAN, 256>>>();
    convert_kernel<<<(N_EDGES + 255) / 256, 256>>>(ei);
    scan1_kernel<<<NB_SCAN, 256>>>();
    scan2_kernel<<<1, 256>>>();
    scan3_kernel<<<NB_SCAN, 256>>>();
    scatter_kernel<<<(N_EDGES + 255) / 256, 256>>>();

    fold_kernel<<<1, 256>>>(node_w, node_b, att_w);
    alpha_kernel<<<(N_NODES * 16 + 255) / 256, 256>>>(x);

    gat_kernel<<<(N_NODES * 32 + 255) / 256, 256>>>(x, out);

    out_gemm_kernel<<<(N_NODES + BM - 1) / BM, 256>>>(out_w, out_b, out);
}